// round 2
// baseline (speedup 1.0000x reference)
#include <cuda_runtime.h>
#include <math.h>

#define N_PTS 32768
#define DY    3
#define H     64
#define NBLK  128       // step-kernel blocks
#define TPB   256       // step-kernel threads/block  (NBLK*TPB == N_PTS)
#define NELEM (N_PTS*DY)
#define MAX_STEPS 24

// ---------------- persistent device state (no allocation) ----------------
__device__ float g_t;
__device__ float g_dt;
__device__ int   g_upd;
__device__ float g_ynew[NELEM];
__device__ float g_partials[NBLK];

// ---------------- dopri5 tableau (match jax: python-double -> f32) --------
__constant__ float cC[7] = {
    0.0f, 0.2f, 0.3f, 0.8f, (float)(8.0/9.0), 1.0f, 1.0f
};
__constant__ float cA[7][6] = {
    {0,0,0,0,0,0},
    {(float)(1.0/5.0),0,0,0,0,0},
    {(float)(3.0/40.0),(float)(9.0/40.0),0,0,0,0},
    {(float)(44.0/45.0),(float)(-56.0/15.0),(float)(32.0/9.0),0,0,0},
    {(float)(19372.0/6561.0),(float)(-25360.0/2187.0),(float)(64448.0/6561.0),(float)(-212.0/729.0),0,0},
    {(float)(9017.0/3168.0),(float)(-355.0/33.0),(float)(46732.0/5247.0),(float)(49.0/176.0),(float)(-5103.0/18656.0),0},
    {(float)(35.0/384.0),0.0f,(float)(500.0/1113.0),(float)(125.0/192.0),(float)(-2187.0/6784.0),(float)(11.0/84.0)},
};
__constant__ float cB[7] = {
    (float)(35.0/384.0), 0.0f, (float)(500.0/1113.0), (float)(125.0/192.0),
    (float)(-2187.0/6784.0), (float)(11.0/84.0), 0.0f
};
__constant__ float cE[7] = {
    (float)(35.0/384.0 - 5179.0/57600.0),
    0.0f,
    (float)(500.0/1113.0 - 7571.0/16695.0),
    (float)(125.0/192.0 - 393.0/640.0),
    (float)(-2187.0/6784.0 + 92097.0/339200.0),
    (float)(11.0/84.0 - 187.0/2100.0),
    (float)(-1.0/40.0)
};

// ---------------- MLP: x(3)+t -> tanh(64) -> tanh(64) -> 3 ---------------
// Weights pre-transposed in shared memory for float4 broadcast LDS.
__device__ __forceinline__ float3 mlp_eval(
    const float4* __restrict__ sW1t,   // [H] : (W1[0][j],W1[1][j],W1[2][j],W1[3][j])
    const float*  __restrict__ sb1,    // [H]
    const float*  __restrict__ sW2t,   // [H*H] : [j][k] (transposed)
    const float*  __restrict__ sb2,    // [H]
    const float4* __restrict__ sW3,    // [H] : (W3[j][0],W3[j][1],W3[j][2],0)
    const float*  __restrict__ sb3,    // [3]
    float t, float x0, float x1, float x2)
{
    float h1[H];
#pragma unroll
    for (int j = 0; j < H; j++) {
        float4 w = sW1t[j];
        float a = fmaf(t, w.w, sb1[j]);
        a = fmaf(x2, w.z, a);
        a = fmaf(x1, w.y, a);
        a = fmaf(x0, w.x, a);
        h1[j] = tanhf(a);
    }
    float o0 = sb3[0], o1 = sb3[1], o2 = sb3[2];
#pragma unroll
    for (int j = 0; j < H; j++) {
        const float4* wr = (const float4*)(sW2t + j * H);
        float a0 = sb2[j], a1 = 0.0f, a2 = 0.0f, a3 = 0.0f;
#pragma unroll
        for (int k4 = 0; k4 < H / 4; k4 += 4) {
            float4 w0 = wr[k4 + 0];
            a0 = fmaf(h1[4*k4 + 0], w0.x, a0);
            a0 = fmaf(h1[4*k4 + 1], w0.y, a0);
            a0 = fmaf(h1[4*k4 + 2], w0.z, a0);
            a0 = fmaf(h1[4*k4 + 3], w0.w, a0);
            float4 w1 = wr[k4 + 1];
            a1 = fmaf(h1[4*k4 + 4], w1.x, a1);
            a1 = fmaf(h1[4*k4 + 5], w1.y, a1);
            a1 = fmaf(h1[4*k4 + 6], w1.z, a1);
            a1 = fmaf(h1[4*k4 + 7], w1.w, a1);
            float4 w2 = wr[k4 + 2];
            a2 = fmaf(h1[4*k4 + 8], w2.x, a2);
            a2 = fmaf(h1[4*k4 + 9], w2.y, a2);
            a2 = fmaf(h1[4*k4 +10], w2.z, a2);
            a2 = fmaf(h1[4*k4 +11], w2.w, a2);
            float4 w3v = wr[k4 + 3];
            a3 = fmaf(h1[4*k4 +12], w3v.x, a3);
            a3 = fmaf(h1[4*k4 +13], w3v.y, a3);
            a3 = fmaf(h1[4*k4 +14], w3v.z, a3);
            a3 = fmaf(h1[4*k4 +15], w3v.w, a3);
        }
        float h2 = tanhf((a0 + a1) + (a2 + a3));
        float4 w3 = sW3[j];
        o0 = fmaf(h2, w3.x, o0);
        o1 = fmaf(h2, w3.y, o1);
        o2 = fmaf(h2, w3.z, o2);
    }
    return make_float3(o0, o1, o2);
}

// ---------------- kernels -------------------------------------------------
__global__ void ode_init_kernel(const float* __restrict__ yin, float* __restrict__ y)
{
    int i = blockIdx.x * blockDim.x + threadIdx.x;
    if (i < NELEM) y[i] = yin[i];
    if (i == 0) { g_t = 0.0f; g_dt = 0.05f; g_upd = 0; }
}

__global__ void __launch_bounds__(TPB)
ode_step_kernel(const float* __restrict__ y,
                const float* __restrict__ W1, const float* __restrict__ b1,
                const float* __restrict__ W2, const float* __restrict__ b2,
                const float* __restrict__ W3, const float* __restrict__ b3)
{
    const float t  = g_t;
    const float rem = 1.0f - t;
    if (!(rem > 1e-9f)) return;           // inactive step: no state changes (matches ref)
    const float dt  = g_dt;
    const float dtc = fminf(dt, rem);

    __shared__ float4 sW1t[H];
    __shared__ float  sb1[H];
    __shared__ float  sW2t[H * H];
    __shared__ float  sb2[H];
    __shared__ float4 sW3[H];
    __shared__ float  sb3[4];
    __shared__ float  red[TPB];

    const int tid = threadIdx.x;
    for (int idx = tid; idx < H * H; idx += TPB) {
        int j = idx / H, k = idx % H;
        sW2t[j * H + k] = W2[k * H + j];
    }
    if (tid < H) {
        sW1t[tid] = make_float4(W1[0 * H + tid], W1[1 * H + tid], W1[2 * H + tid], W1[3 * H + tid]);
        sb1[tid] = b1[tid];
        sb2[tid] = b2[tid];
        sW3[tid] = make_float4(W3[tid * 3 + 0], W3[tid * 3 + 1], W3[tid * 3 + 2], 0.0f);
    }
    if (tid < 3) sb3[tid] = b3[tid];
    __syncthreads();

    const int n = blockIdx.x * TPB + tid;
    float y0 = y[3 * n + 0];
    float y1 = y[3 * n + 1];
    float y2 = y[3 * n + 2];

    float kb[7][3];
#pragma unroll 1
    for (int i = 0; i < 7; i++) {
        float yi0 = y0, yi1 = y1, yi2 = y2;
        for (int j = 0; j < i; j++) {
            float c = dtc * cA[i][j];
            yi0 += c * kb[j][0];
            yi1 += c * kb[j][1];
            yi2 += c * kb[j][2];
        }
        float3 f = mlp_eval(sW1t, sb1, sW2t, sb2, sW3, sb3,
                            t + cC[i] * dtc, yi0, yi1, yi2);
        kb[i][0] = f.x; kb[i][1] = f.y; kb[i][2] = f.z;
    }

    float yn0 = y0, yn1 = y1, yn2 = y2;
    float ye0 = 0.0f, ye1 = 0.0f, ye2 = 0.0f;
    for (int i = 0; i < 7; i++) {
        float cb = dtc * cB[i];
        float ce = dtc * cE[i];
        yn0 += cb * kb[i][0]; yn1 += cb * kb[i][1]; yn2 += cb * kb[i][2];
        ye0 += ce * kb[i][0]; ye1 += ce * kb[i][1]; ye2 += ce * kb[i][2];
    }

    g_ynew[3 * n + 0] = yn0;
    g_ynew[3 * n + 1] = yn1;
    g_ynew[3 * n + 2] = yn2;

    float local = 0.0f;
    {
        float tol = 1e-5f + 1e-5f * fmaxf(fabsf(y0), fabsf(yn0));
        float r = ye0 / tol; local += r * r;
    }
    {
        float tol = 1e-5f + 1e-5f * fmaxf(fabsf(y1), fabsf(yn1));
        float r = ye1 / tol; local += r * r;
    }
    {
        float tol = 1e-5f + 1e-5f * fmaxf(fabsf(y2), fabsf(yn2));
        float r = ye2 / tol; local += r * r;
    }

    red[tid] = local;
    __syncthreads();
    for (int s = TPB / 2; s > 0; s >>= 1) {
        if (tid < s) red[tid] += red[tid + s];
        __syncthreads();
    }
    if (tid == 0) g_partials[blockIdx.x] = red[0];
}

__global__ void ode_reduce_kernel()
{
    __shared__ float red[NBLK];
    const int tid = threadIdx.x;
    const float t  = g_t;
    const float dt = g_dt;
    const float rem = 1.0f - t;
    const bool active = rem > 1e-9f;
    if (!active) { if (tid == 0) g_upd = 0; return; }

    red[tid] = g_partials[tid];
    __syncthreads();
    for (int s = NBLK / 2; s > 0; s >>= 1) {
        if (tid < s) red[tid] += red[tid + s];
        __syncthreads();
    }
    if (tid == 0) {
        float mean = red[0] / (float)NELEM;
        float err = sqrtf(mean);
        err = fmaxf(err, 1e-10f);
        bool accept = err <= 1.0f;
        float factor = 0.9f * powf(err, -0.2f);
        factor = fminf(fmaxf(factor, 0.2f), 10.0f);
        float dtc = fminf(dt, rem);
        if (accept) { g_t = t + dtc; g_upd = 1; }
        else        { g_upd = 0; }
        g_dt = dtc * factor;
    }
}

__global__ void ode_update_kernel(float* __restrict__ y)
{
    if (!g_upd) return;
    int i = blockIdx.x * blockDim.x + threadIdx.x;
    if (i < NELEM) y[i] = g_ynew[i];
}

// ---------------- launch --------------------------------------------------
extern "C" void kernel_launch(void* const* d_in, const int* in_sizes, int n_in,
                              void* d_out, int out_size)
{
    const float* y_in = (const float*)d_in[0];
    const float* W1   = (const float*)d_in[1];
    const float* b1   = (const float*)d_in[2];
    const float* W2   = (const float*)d_in[3];
    const float* b2   = (const float*)d_in[4];
    const float* W3   = (const float*)d_in[5];
    const float* b3   = (const float*)d_in[6];
    float* y = (float*)d_out;

    ode_init_kernel<<<(NELEM + 255) / 256, 256>>>(y_in, y);
    for (int s = 0; s < MAX_STEPS; s++) {
        ode_step_kernel<<<NBLK, TPB>>>(y, W1, b1, W2, b2, W3, b3);
        ode_reduce_kernel<<<1, NBLK>>>();
        ode_update_kernel<<<(NELEM + 255) / 256, 256>>>(y);
    }
}

// round 3
// speedup vs baseline: 1.3677x; 1.3677x over previous
#include <cuda_runtime.h>
#include <math.h>

#define N_PTS 32768
#define H     64
#define NBLK  128
#define TPB   256
#define NELEM (N_PTS*3)
#define MAX_STEPS 24

// ---------------- persistent device state (no allocation) ----------------
__device__ volatile int   g_count[MAX_STEPS];
__device__ volatile float g_partials[2][NBLK];

// ---------------- dopri5 tableau ------------------------------------------
__constant__ float cC[7] = { 0.0f, 0.2f, 0.3f, 0.8f, (float)(8.0/9.0), 1.0f, 1.0f };
__constant__ float cA[7][6] = {
    {0,0,0,0,0,0},
    {(float)(1.0/5.0),0,0,0,0,0},
    {(float)(3.0/40.0),(float)(9.0/40.0),0,0,0,0},
    {(float)(44.0/45.0),(float)(-56.0/15.0),(float)(32.0/9.0),0,0,0},
    {(float)(19372.0/6561.0),(float)(-25360.0/2187.0),(float)(64448.0/6561.0),(float)(-212.0/729.0),0,0},
    {(float)(9017.0/3168.0),(float)(-355.0/33.0),(float)(46732.0/5247.0),(float)(49.0/176.0),(float)(-5103.0/18656.0),0},
    {(float)(35.0/384.0),0.0f,(float)(500.0/1113.0),(float)(125.0/192.0),(float)(-2187.0/6784.0),(float)(11.0/84.0)},
};
__constant__ float cB[7] = {
    (float)(35.0/384.0), 0.0f, (float)(500.0/1113.0), (float)(125.0/192.0),
    (float)(-2187.0/6784.0), (float)(11.0/84.0), 0.0f
};
__constant__ float cE[7] = {
    (float)(35.0/384.0 - 5179.0/57600.0),
    0.0f,
    (float)(500.0/1113.0 - 7571.0/16695.0),
    (float)(125.0/192.0 - 393.0/640.0),
    (float)(-2187.0/6784.0 + 92097.0/339200.0),
    (float)(11.0/84.0 - 187.0/2100.0),
    (float)(-1.0/40.0)
};

// ---------------- fast tanh: ex2.approx + rcp.approx + 1 Newton ----------
__device__ __forceinline__ float fast_tanh(float x)
{
    // tanh(x) = 1 - 2/(exp(2x)+1).  Clamp so exp stays finite (tanh(9)==1 in fp32).
    x = fminf(fmaxf(x, -9.0f), 9.0f);
    float e;
    asm("ex2.approx.f32 %0, %1;" : "=f"(e) : "f"(x * 2.8853900817779268f)); // 2*log2(e)
    float d = e + 1.0f;
    float r;
    asm("rcp.approx.f32 %0, %1;" : "=f"(r) : "f"(d));
    r = r * fmaf(-d, r, 2.0f);              // Newton: full fp32 precision on 1/d
    return fmaf(-2.0f, r, 1.0f);
}

// ---------------- MLP: x(3)+t -> tanh(64) -> tanh(64) -> 3 ---------------
__device__ __forceinline__ float3 mlp_eval(
    const float4* __restrict__ sW1t, const float* __restrict__ sb1,
    const float*  __restrict__ sW2t, const float* __restrict__ sb2,
    const float4* __restrict__ sW3,  const float* __restrict__ sb3,
    float t, float x0, float x1, float x2)
{
    float h1[H];
#pragma unroll
    for (int j = 0; j < H; j++) {
        float4 w = sW1t[j];
        float a = fmaf(t, w.w, sb1[j]);
        a = fmaf(x2, w.z, a);
        a = fmaf(x1, w.y, a);
        a = fmaf(x0, w.x, a);
        h1[j] = fast_tanh(a);
    }
    float o0 = sb3[0], o1 = sb3[1], o2 = sb3[2];
#pragma unroll
    for (int j = 0; j < H; j++) {
        const float4* wr = (const float4*)(sW2t + j * H);
        float a0 = sb2[j], a1 = 0.0f, a2 = 0.0f, a3 = 0.0f;
#pragma unroll
        for (int k4 = 0; k4 < H / 4; k4 += 4) {
            float4 w0 = wr[k4 + 0];
            a0 = fmaf(h1[4*k4 + 0], w0.x, a0);
            a0 = fmaf(h1[4*k4 + 1], w0.y, a0);
            a0 = fmaf(h1[4*k4 + 2], w0.z, a0);
            a0 = fmaf(h1[4*k4 + 3], w0.w, a0);
            float4 w1 = wr[k4 + 1];
            a1 = fmaf(h1[4*k4 + 4], w1.x, a1);
            a1 = fmaf(h1[4*k4 + 5], w1.y, a1);
            a1 = fmaf(h1[4*k4 + 6], w1.z, a1);
            a1 = fmaf(h1[4*k4 + 7], w1.w, a1);
            float4 w2 = wr[k4 + 2];
            a2 = fmaf(h1[4*k4 + 8], w2.x, a2);
            a2 = fmaf(h1[4*k4 + 9], w2.y, a2);
            a2 = fmaf(h1[4*k4 +10], w2.z, a2);
            a2 = fmaf(h1[4*k4 +11], w2.w, a2);
            float4 w3v = wr[k4 + 3];
            a3 = fmaf(h1[4*k4 +12], w3v.x, a3);
            a3 = fmaf(h1[4*k4 +13], w3v.y, a3);
            a3 = fmaf(h1[4*k4 +14], w3v.z, a3);
            a3 = fmaf(h1[4*k4 +15], w3v.w, a3);
        }
        float h2 = fast_tanh((a0 + a1) + (a2 + a3));
        float4 w3 = sW3[j];
        o0 = fmaf(h2, w3.x, o0);
        o1 = fmaf(h2, w3.y, o1);
        o2 = fmaf(h2, w3.z, o2);
    }
    return make_float3(o0, o1, o2);
}

// ---------------- init: reset barrier counters every replay ---------------
__global__ void ode_init_kernel()
{
    int i = threadIdx.x;
    if (i < MAX_STEPS) g_count[i] = 0;
}

// ---------------- persistent fused integrator -----------------------------
__global__ void __launch_bounds__(TPB)
ode_persistent_kernel(const float* __restrict__ yin,
                      const float* __restrict__ W1, const float* __restrict__ b1,
                      const float* __restrict__ W2, const float* __restrict__ b2,
                      const float* __restrict__ W3, const float* __restrict__ b3,
                      float* __restrict__ yout)
{
    __shared__ float4 sW1t[H];
    __shared__ float  sb1[H];
    __shared__ float  sW2t[H * H];
    __shared__ float  sb2[H];
    __shared__ float4 sW3[H];
    __shared__ float  sb3[4];
    __shared__ float  red[TPB];

    const int tid = threadIdx.x;
    const int bid = blockIdx.x;

    for (int idx = tid; idx < H * H; idx += TPB) {
        int j = idx / H, k = idx % H;
        sW2t[j * H + k] = W2[k * H + j];
    }
    if (tid < H) {
        sW1t[tid] = make_float4(W1[0*H + tid], W1[1*H + tid], W1[2*H + tid], W1[3*H + tid]);
        sb1[tid] = b1[tid];
        sb2[tid] = b2[tid];
        sW3[tid] = make_float4(W3[tid*3 + 0], W3[tid*3 + 1], W3[tid*3 + 2], 0.0f);
    }
    if (tid < 3) sb3[tid] = b3[tid];
    __syncthreads();

    const int n = bid * TPB + tid;
    float y0 = yin[3*n + 0];
    float y1 = yin[3*n + 1];
    float y2 = yin[3*n + 2];

    float t  = 0.0f;
    float dt = 0.05f;

    for (int s = 0; s < MAX_STEPS; s++) {
        const float rem = 1.0f - t;
        if (!(rem > 1e-9f)) break;                 // identical in all blocks (deterministic)
        const float dtc = fminf(dt, rem);

        // ---- 7 dopri5 stages ----
        float kb[7][3];
#pragma unroll 1
        for (int i = 0; i < 7; i++) {
            float yi0 = y0, yi1 = y1, yi2 = y2;
            for (int j = 0; j < i; j++) {
                float c = dtc * cA[i][j];
                yi0 += c * kb[j][0];
                yi1 += c * kb[j][1];
                yi2 += c * kb[j][2];
            }
            float3 f = mlp_eval(sW1t, sb1, sW2t, sb2, sW3, sb3,
                                t + cC[i] * dtc, yi0, yi1, yi2);
            kb[i][0] = f.x; kb[i][1] = f.y; kb[i][2] = f.z;
        }

        float yn0 = y0, yn1 = y1, yn2 = y2;
        float ye0 = 0.0f, ye1 = 0.0f, ye2 = 0.0f;
        for (int i = 0; i < 7; i++) {
            float cb = dtc * cB[i];
            float ce = dtc * cE[i];
            yn0 += cb * kb[i][0]; yn1 += cb * kb[i][1]; yn2 += cb * kb[i][2];
            ye0 += ce * kb[i][0]; ye1 += ce * kb[i][1]; ye2 += ce * kb[i][2];
        }

        // ---- per-thread error contribution, block tree reduce ----
        float local;
        {
            float tol0 = 1e-5f + 1e-5f * fmaxf(fabsf(y0), fabsf(yn0));
            float tol1 = 1e-5f + 1e-5f * fmaxf(fabsf(y1), fabsf(yn1));
            float tol2 = 1e-5f + 1e-5f * fmaxf(fabsf(y2), fabsf(yn2));
            float r0 = ye0 / tol0, r1 = ye1 / tol1, r2 = ye2 / tol2;
            local = r0*r0 + (r1*r1 + r2*r2);
        }
        red[tid] = local;
        __syncthreads();
        for (int sh = TPB / 2; sh > 0; sh >>= 1) {
            if (tid < sh) red[tid] += red[tid + sh];
            __syncthreads();
        }

        // ---- grid barrier: publish partial, arrive, spin ----
        const int buf = s & 1;
        if (tid == 0) {
            g_partials[buf][bid] = red[0];
            __threadfence();                        // release partial before arrival
            atomicAdd((int*)&g_count[s], 1);
            while (g_count[s] < NBLK) { }           // volatile spin
            __threadfence();                        // acquire all partials
        }
        __syncthreads();

        // ---- redundant, deterministic controller in every block ----
        if (tid < NBLK) red[tid] = g_partials[buf][tid];   // volatile: bypass stale L1
        __syncthreads();
        for (int sh = NBLK / 2; sh > 0; sh >>= 1) {
            if (tid < sh) red[tid] += red[tid + sh];
            __syncthreads();
        }
        float total = red[0];
        __syncthreads();                            // red reusable next iter

        float err = sqrtf(total / (float)NELEM);
        err = fmaxf(err, 1e-10f);
        bool accept = err <= 1.0f;
        float factor = 0.9f * powf(err, -0.2f);
        factor = fminf(fmaxf(factor, 0.2f), 10.0f);
        if (accept) { t += dtc; y0 = yn0; y1 = yn1; y2 = yn2; }
        dt = dtc * factor;
    }

    yout[3*n + 0] = y0;
    yout[3*n + 1] = y1;
    yout[3*n + 2] = y2;
}

// ---------------- launch --------------------------------------------------
extern "C" void kernel_launch(void* const* d_in, const int* in_sizes, int n_in,
                              void* d_out, int out_size)
{
    const float* y_in = (const float*)d_in[0];
    const float* W1   = (const float*)d_in[1];
    const float* b1   = (const float*)d_in[2];
    const float* W2   = (const float*)d_in[3];
    const float* b2   = (const float*)d_in[4];
    const float* W3   = (const float*)d_in[5];
    const float* b3   = (const float*)d_in[6];
    float* y = (float*)d_out;

    ode_init_kernel<<<1, 32>>>();
    ode_persistent_kernel<<<NBLK, TPB>>>(y_in, W1, b1, W2, b2, W3, b3, y);
}